// round 1
// baseline (speedup 1.0000x reference)
#include <cuda_runtime.h>

#define Bn 16
#define Cn 512
#define Hn 64
#define Wn 64
#define Rn 64

// Scratch (device globals; no allocation allowed)
__device__ float g_sumC[Bn*Cn];
__device__ float g_partW[Bn*Cn*Wn];
__device__ float g_partH[Bn*Cn*Hn];
__device__ float g_cA[Bn*Rn*Cn];    // c_out laid out [b][r][c]
__device__ float g_wout[Bn*Rn*Wn];  // [b][r][w]
__device__ float g_hout[Bn*Rn*Hn];  // [b][r][h]

// ---------------------------------------------------------------------------
// K1: per-(b,c) plane reductions: total sum, per-w column sums, per-h row sums
// ---------------------------------------------------------------------------
__global__ __launch_bounds__(256) void k_reduce(const float* __restrict__ x) {
    int plane = blockIdx.x;  // b*Cn + c
    const float4* x4 = (const float4*)(x + (size_t)plane * 4096);
    int tid = threadIdx.x;

    __shared__ float4 s4[256];
    __shared__ float  sh[256][4];

    float4 wacc = make_float4(0.f, 0.f, 0.f, 0.f);
    float hacc[4];
#pragma unroll
    for (int k = 0; k < 4; k++) {
        float4 f = x4[tid + 256 * k];        // w4 = tid%16 fixed, h = tid/16 + 16k
        wacc.x += f.x; wacc.y += f.y; wacc.z += f.z; wacc.w += f.w;
        hacc[k] = f.x + f.y + f.z + f.w;
    }
    s4[tid] = wacc;
    sh[tid][0] = hacc[0]; sh[tid][1] = hacc[1];
    sh[tid][2] = hacc[2]; sh[tid][3] = hacc[3];
    __syncthreads();

    if (tid < 16) {
        float4 t = s4[tid];
#pragma unroll
        for (int j = 1; j < 16; j++) {
            float4 u = s4[tid + 16 * j];
            t.x += u.x; t.y += u.y; t.z += u.z; t.w += u.w;
        }
        ((float4*)g_partW)[plane * 16 + tid] = t;
        s4[tid] = t;
    }
    if (tid >= 64 && tid < 128) {
        int h = tid - 64;
        int base = (h & 15) * 16;
        int k = h >> 4;
        float s = 0.f;
#pragma unroll
        for (int j = 0; j < 16; j++) s += sh[base + j][k];
        g_partH[plane * 64 + h] = s;
    }
    __syncthreads();
    if (tid == 0) {
        float tot = 0.f;
#pragma unroll
        for (int j = 0; j < 16; j++) {
            float4 u = s4[j];
            tot += u.x + u.y + u.z + u.w;
        }
        g_sumC[plane] = tot;
    }
}

// ---------------------------------------------------------------------------
// K2: finish gap means, 3-tap convs + PReLU for the three branches
// ---------------------------------------------------------------------------
__global__ __launch_bounds__(256) void k_branches(
    const float* __restrict__ w_c, const float* __restrict__ a_c,
    const float* __restrict__ w_w, const float* __restrict__ a_w,
    const float* __restrict__ w_h, const float* __restrict__ a_h) {
    int b = blockIdx.x, tid = threadIdx.x;
    __shared__ float gc[Cn + 2];
    __shared__ float gw[Wn + 2];
    __shared__ float gh[Hn + 2];
    __shared__ float red[4][64];

    for (int i = tid; i < Cn; i += 256)
        gc[i + 1] = g_sumC[b * Cn + i] * (1.f / 4096.f);
    if (tid == 0) {
        gc[0] = 0.f; gc[Cn + 1] = 0.f;
        gw[0] = 0.f; gw[Wn + 1] = 0.f;
        gh[0] = 0.f; gh[Hn + 1] = 0.f;
    }
    // gap_w = sum over (c,h) / 32768
    {
        int q = tid >> 6, w = tid & 63;
        float s = 0.f;
        const float* p = g_partW + ((size_t)(b * Cn + q * 128)) * 64 + w;
#pragma unroll 4
        for (int c = 0; c < 128; c++) s += p[c * 64];
        red[q][w] = s;
    }
    __syncthreads();
    if (tid < 64)
        gw[tid + 1] = (red[0][tid] + red[1][tid] + red[2][tid] + red[3][tid]) * (1.f / 32768.f);
    __syncthreads();
    // gap_h
    {
        int q = tid >> 6, hh = tid & 63;
        float s = 0.f;
        const float* p = g_partH + ((size_t)(b * Cn + q * 128)) * 64 + hh;
#pragma unroll 4
        for (int c = 0; c < 128; c++) s += p[c * 64];
        red[q][hh] = s;
    }
    __syncthreads();
    if (tid < 64)
        gh[tid + 1] = (red[0][tid] + red[1][tid] + red[2][tid] + red[3][tid]) * (1.f / 32768.f);
    __syncthreads();

    float acv = a_c[0], awv = a_w[0], ahv = a_h[0];
    // channel branch: out[r][c] = conv3(gap_c), prelu
    for (int i = tid; i < Rn * Cn; i += 256) {
        int r = i >> 9, c = i & 511;
        float v = w_c[r * 3] * gc[c] + w_c[r * 3 + 1] * gc[c + 1] + w_c[r * 3 + 2] * gc[c + 2];
        g_cA[b * Rn * Cn + i] = (v >= 0.f) ? v : acv * v;
    }
    // width + height branches
    for (int i = tid; i < Rn * Wn; i += 256) {
        int r = i >> 6, w = i & 63;
        float v = w_w[r * 3] * gw[w] + w_w[r * 3 + 1] * gw[w + 1] + w_w[r * 3 + 2] * gw[w + 2];
        g_wout[b * Rn * Wn + i] = (v >= 0.f) ? v : awv * v;
        float v2 = w_h[r * 3] * gh[w] + w_h[r * 3 + 1] * gh[w + 1] + w_h[r * 3 + 2] * gh[w + 2];
        g_hout[b * Rn * Hn + i] = (v2 >= 0.f) ? v2 : ahv * v2;
    }
}

// ---------------------------------------------------------------------------
// K3: per-(b,h) block: GEMM cp = c_out^T @ (h_out*w_out), softmax over c,
// fused 3x3x3 conv3d + res*gcrw + x epilogue.
// ---------------------------------------------------------------------------
#define CP_STRIDE 68
#define SM_BYTES  190464   // 47616 floats

__global__ void __launch_bounds__(512, 1) k_main(
    const float* __restrict__ x, const float* __restrict__ w3d,
    float* __restrict__ out) {
    extern __shared__ float sm[];
    int h = blockIdx.x, b = blockIdx.y;
    int tid = threadIdx.x;

    float* At = sm;            // [64][512]  (GEMM phase only)
    float* S  = sm + 32768;    // [64][64]   (GEMM phase only)

    // Phase 0: stage A = c_out[b] (r-major), S[r][w] = h_out[r][h]*w_out[r][w]
    {
        const float4* src = (const float4*)(g_cA + (size_t)b * Rn * Cn);
        float4* dst = (float4*)At;
#pragma unroll
        for (int i = tid; i < 8192; i += 512) dst[i] = src[i];
        const float* ho = g_hout + b * Rn * Hn;
        const float* wo = g_wout + b * Rn * Wn;
        for (int i = tid; i < 4096; i += 512) {
            int r = i >> 6, w = i & 63;
            S[i] = ho[r * 64 + h] * wo[r * 64 + w];
        }
    }
    __syncthreads();

    // Phase 1: register-tiled GEMM. Thread owns 8 c x 8 w outputs.
    float acc[8][8];
#pragma unroll
    for (int i = 0; i < 8; i++)
#pragma unroll
        for (int j = 0; j < 8; j++) acc[i][j] = 0.f;

    int cT = tid >> 3, wT = tid & 7;
    const float* Ab = At + cT * 8;
    const float* Bb = S + wT * 8;
#pragma unroll 2
    for (int r = 0; r < 64; r++) {
        float4 a0 = *(const float4*)(Ab + r * 512);
        float4 a1 = *(const float4*)(Ab + r * 512 + 4);
        float4 b0 = *(const float4*)(Bb + r * 64);
        float4 b1 = *(const float4*)(Bb + r * 64 + 4);
        float av[8] = {a0.x, a0.y, a0.z, a0.w, a1.x, a1.y, a1.z, a1.w};
        float bv[8] = {b0.x, b0.y, b0.z, b0.w, b1.x, b1.y, b1.z, b1.w};
#pragma unroll
        for (int i = 0; i < 8; i++)
#pragma unroll
            for (int j = 0; j < 8; j++) acc[i][j] += av[i] * bv[j];
    }
    __syncthreads();

    // Phase 2: write cp[c][w] (stride 68 keeps float4 alignment, low conflicts)
    float* cp = sm;
#pragma unroll
    for (int i = 0; i < 8; i++) {
        int c = cT * 8 + i;
        float* p = cp + c * CP_STRIDE + wT * 8;
        *(float4*)(p)     = make_float4(acc[i][0], acc[i][1], acc[i][2], acc[i][3]);
        *(float4*)(p + 4) = make_float4(acc[i][4], acc[i][5], acc[i][6], acc[i][7]);
    }
    __syncthreads();

    float* xs   = sm + 34816;  // [66][3][64] conv staging
    float* smax = sm + 47488;  // [64]
    float* sinv = sm + 47552;  // [64]

    // Phase 3: softmax stats over c (one w column per warp x 4)
    {
        int warp = tid >> 5, lane = tid & 31;
#pragma unroll
        for (int t = 0; t < 4; t++) {
            int w = warp * 4 + t;
            float vals[16], m = -3.4e38f;
#pragma unroll
            for (int j = 0; j < 16; j++) {
                vals[j] = cp[(lane + 32 * j) * CP_STRIDE + w];
                m = fmaxf(m, vals[j]);
            }
#pragma unroll
            for (int o = 16; o; o >>= 1) m = fmaxf(m, __shfl_xor_sync(0xffffffffu, m, o));
            float s = 0.f;
#pragma unroll
            for (int j = 0; j < 16; j++) s += __expf(vals[j] - m);
#pragma unroll
            for (int o = 16; o; o >>= 1) s += __shfl_xor_sync(0xffffffffu, s, o);
            if (lane == 0) { smax[w] = m; sinv[w] = 1.f / s; }
        }
    }
    __syncthreads();

    // Preload conv weights + per-w softmax stats into registers
    float w3[27];
#pragma unroll
    for (int t = 0; t < 27; t++) w3[t] = __ldg(w3d + t);
    int cl = tid >> 3, wg = tid & 7;
    float mw[8], iv[8];
#pragma unroll
    for (int j = 0; j < 8; j++) {
        mw[j] = smax[wg * 8 + j];
        iv[j] = sinv[wg * 8 + j];
    }

    // Phase 4: conv3d + softmax scale + residual, c in chunks of 64
    const float4* x4 = (const float4*)x;
    for (int c0 = 0; c0 < 512; c0 += 64) {
        __syncthreads();
        // stage x[b, c0-1..c0+64, h-1..h+1, :] with zero padding
        for (int i = tid; i < 3168; i += 512) {
            int w4 = i & 15, rem = i >> 4;
            int dh = rem % 3, cc = rem / 3;
            int cg = c0 - 1 + cc, hg = h - 1 + dh;
            float4 v = make_float4(0.f, 0.f, 0.f, 0.f);
            if ((unsigned)cg < 512u && (unsigned)hg < 64u)
                v = x4[((size_t)(b * 512 + cg) * 64 + hg) * 16 + w4];
            ((float4*)xs)[i] = v;
        }
        __syncthreads();

        int c = c0 + cl;
        float res[8];
#pragma unroll
        for (int j = 0; j < 8; j++) res[j] = 0.f;
        float4 xi0 = make_float4(0.f, 0.f, 0.f, 0.f), xi1 = xi0;
#pragma unroll
        for (int dc = 0; dc < 3; dc++)
#pragma unroll
            for (int dh = 0; dh < 3; dh++) {
                const float* row = xs + (cl + dc) * 192 + dh * 64 + wg * 8;
                float4 m0 = *(const float4*)row;
                float4 m1 = *(const float4*)(row + 4);
                float left  = (wg == 0) ? 0.f : row[-1];
                float right = (wg == 7) ? 0.f : row[8];
                if (dc == 1 && dh == 1) { xi0 = m0; xi1 = m1; }
                float v[10] = {left, m0.x, m0.y, m0.z, m0.w,
                               m1.x, m1.y, m1.z, m1.w, right};
                int t = (dc * 3 + dh) * 3;
                float k0 = w3[t], k1 = w3[t + 1], k2 = w3[t + 2];
#pragma unroll
                for (int j = 0; j < 8; j++)
                    res[j] += k0 * v[j] + k1 * v[j + 1] + k2 * v[j + 2];
            }

        const float* cr = cp + c * CP_STRIDE + wg * 8;
        float4 cv0 = *(const float4*)cr;
        float4 cv1 = *(const float4*)(cr + 4);
        float cpv[8] = {cv0.x, cv0.y, cv0.z, cv0.w, cv1.x, cv1.y, cv1.z, cv1.w};
        float xin[8] = {xi0.x, xi0.y, xi0.z, xi0.w, xi1.x, xi1.y, xi1.z, xi1.w};
        float o[8];
#pragma unroll
        for (int j = 0; j < 8; j++)
            o[j] = res[j] * (__expf(cpv[j] - mw[j]) * iv[j]) + xin[j];

        float* op = out + (((size_t)(b * 512 + c) * 64 + h) * 64 + wg * 8);
        *(float4*)(op)     = make_float4(o[0], o[1], o[2], o[3]);
        *(float4*)(op + 4) = make_float4(o[4], o[5], o[6], o[7]);
    }
}

// ---------------------------------------------------------------------------
extern "C" void kernel_launch(void* const* d_in, const int* in_sizes, int n_in,
                              void* d_out, int out_size) {
    const float* x   = (const float*)d_in[0];
    const float* w_c = (const float*)d_in[1];
    const float* a_c = (const float*)d_in[2];
    const float* w_w = (const float*)d_in[3];
    const float* a_w = (const float*)d_in[4];
    const float* w_h = (const float*)d_in[5];
    const float* a_h = (const float*)d_in[6];
    const float* w3d = (const float*)d_in[7];
    float* out = (float*)d_out;

    cudaFuncSetAttribute(k_main, cudaFuncAttributeMaxDynamicSharedMemorySize, SM_BYTES);

    k_reduce<<<Bn * Cn, 256>>>(x);
    k_branches<<<Bn, 256>>>(w_c, a_c, w_w, a_w, w_h, a_h);
    dim3 grid(Hn, Bn);
    k_main<<<grid, 512, SM_BYTES>>>(x, w3d, out);
}

// round 4
// speedup vs baseline: 1.4674x; 1.4674x over previous
#include <cuda_runtime.h>
#include <cuda_bf16.h>
#include <cstdint>

#define Bn 16
#define Cn 512
#define Hn 64
#define Wn 64
#define Rn 64
#define A_LD 72   // padded bf16 row stride (144B: 16B-aligned, ldmatrix conflict-free)

// Scratch (device globals; no allocation allowed)
__device__ float g_sumC[Bn*Cn];
__device__ float g_partW[Bn*Cn*Wn];
__device__ float g_partH[Bn*Cn*Hn];
__device__ __align__(16) __nv_bfloat16 g_cAb[Bn*Cn*A_LD];  // A[b][c][r] bf16 padded
__device__ float g_wout[Bn*Rn*Wn];  // [b][r][w]
__device__ float g_hout[Bn*Rn*Hn];  // [b][r][h]

__device__ __forceinline__ unsigned s2u(const void* p) {
    return (unsigned)__cvta_generic_to_shared(p);
}

// ---------------------------------------------------------------------------
// K1: per-(b,c) plane reductions: total sum, per-w column sums, per-h row sums
// ---------------------------------------------------------------------------
__global__ __launch_bounds__(256) void k_reduce(const float* __restrict__ x) {
    int plane = blockIdx.x;  // b*Cn + c
    const float4* x4 = (const float4*)(x + (size_t)plane * 4096);
    int tid = threadIdx.x;

    __shared__ float4 s4[256];
    __shared__ float  sh[256][4];

    float4 wacc = make_float4(0.f, 0.f, 0.f, 0.f);
    float hacc[4];
#pragma unroll
    for (int k = 0; k < 4; k++) {
        float4 f = x4[tid + 256 * k];
        wacc.x += f.x; wacc.y += f.y; wacc.z += f.z; wacc.w += f.w;
        hacc[k] = f.x + f.y + f.z + f.w;
    }
    s4[tid] = wacc;
    sh[tid][0] = hacc[0]; sh[tid][1] = hacc[1];
    sh[tid][2] = hacc[2]; sh[tid][3] = hacc[3];
    __syncthreads();

    if (tid < 16) {
        float4 t = s4[tid];
#pragma unroll
        for (int j = 1; j < 16; j++) {
            float4 u = s4[tid + 16 * j];
            t.x += u.x; t.y += u.y; t.z += u.z; t.w += u.w;
        }
        ((float4*)g_partW)[plane * 16 + tid] = t;
        s4[tid] = t;
    }
    if (tid >= 64 && tid < 128) {
        int h = tid - 64;
        int base = (h & 15) * 16;
        int k = h >> 4;
        float s = 0.f;
#pragma unroll
        for (int j = 0; j < 16; j++) s += sh[base + j][k];
        g_partH[plane * 64 + h] = s;
    }
    __syncthreads();
    if (tid == 0) {
        float tot = 0.f;
#pragma unroll
        for (int j = 0; j < 16; j++) {
            float4 u = s4[j];
            tot += u.x + u.y + u.z + u.w;
        }
        g_sumC[plane] = tot;
    }
}

// ---------------------------------------------------------------------------
// K2: finish gap means, 3-tap convs + PReLU for the three branches
// ---------------------------------------------------------------------------
__global__ __launch_bounds__(256) void k_branches(
    const float* __restrict__ w_c, const float* __restrict__ a_c,
    const float* __restrict__ w_w, const float* __restrict__ a_w,
    const float* __restrict__ w_h, const float* __restrict__ a_h) {
    int b = blockIdx.x, tid = threadIdx.x;
    __shared__ float gc[Cn + 2];
    __shared__ float gw[Wn + 2];
    __shared__ float gh[Hn + 2];
    __shared__ float red[4][64];

    for (int i = tid; i < Cn; i += 256)
        gc[i + 1] = g_sumC[b * Cn + i] * (1.f / 4096.f);
    if (tid == 0) {
        gc[0] = 0.f; gc[Cn + 1] = 0.f;
        gw[0] = 0.f; gw[Wn + 1] = 0.f;
        gh[0] = 0.f; gh[Hn + 1] = 0.f;
    }
    {
        int q = tid >> 6, w = tid & 63;
        float s = 0.f;
        const float* p = g_partW + ((size_t)(b * Cn + q * 128)) * 64 + w;
#pragma unroll 4
        for (int c = 0; c < 128; c++) s += p[c * 64];
        red[q][w] = s;
    }
    __syncthreads();
    if (tid < 64)
        gw[tid + 1] = (red[0][tid] + red[1][tid] + red[2][tid] + red[3][tid]) * (1.f / 32768.f);
    __syncthreads();
    {
        int q = tid >> 6, hh = tid & 63;
        float s = 0.f;
        const float* p = g_partH + ((size_t)(b * Cn + q * 128)) * 64 + hh;
#pragma unroll 4
        for (int c = 0; c < 128; c++) s += p[c * 64];
        red[q][hh] = s;
    }
    __syncthreads();
    if (tid < 64)
        gh[tid + 1] = (red[0][tid] + red[1][tid] + red[2][tid] + red[3][tid]) * (1.f / 32768.f);
    __syncthreads();

    float acv = a_c[0], awv = a_w[0], ahv = a_h[0];
    // channel branch -> bf16 A matrix [c][r] (row stride A_LD)
    for (int i = tid; i < Rn * Cn; i += 256) {
        int r = i >> 9, c = i & 511;
        float v = w_c[r * 3] * gc[c] + w_c[r * 3 + 1] * gc[c + 1] + w_c[r * 3 + 2] * gc[c + 2];
        v = (v >= 0.f) ? v : acv * v;
        g_cAb[((size_t)(b * Cn + c)) * A_LD + r] = __float2bfloat16(v);
    }
    for (int i = tid; i < Rn * Wn; i += 256) {
        int r = i >> 6, w = i & 63;
        float v = w_w[r * 3] * gw[w] + w_w[r * 3 + 1] * gw[w + 1] + w_w[r * 3 + 2] * gw[w + 2];
        g_wout[b * Rn * Wn + i] = (v >= 0.f) ? v : awv * v;
        float v2 = w_h[r * 3] * gh[w] + w_h[r * 3 + 1] * gh[w + 1] + w_h[r * 3 + 2] * gh[w + 2];
        g_hout[b * Rn * Hn + i] = (v2 >= 0.f) ? v2 : ahv * v2;
    }
}

// ---------------------------------------------------------------------------
// K3: per-(b,h) block: tensor-core GEMM cp = A^T(bf16) @ S(bf16), softmax over
// c held in registers, g stored bf16, double-buffered cp.async conv epilogue.
// ---------------------------------------------------------------------------
#define SMO_A    0        // bf16 [512][A_LD]     = 73728 B (dead after MMA)
#define SMO_S    73728    // bf16 [64][A_LD]      = 9216 B
#define SMO_WRED 82944    // f32 [16][64]         = 4096 B
#define SMO_MCOL 87040    // f32 [64]
#define SMO_ICOL 87296    // f32 [64]
#define SMO_XS   87552    // 2 x 12672 f32        = 101376 B
#define SMO_G    0        // bf16 [512][64]       = 65536 B (overlaps A)
#define XS_CHUNK 12672
#define SM_BYTES 188928

__global__ void __launch_bounds__(512, 1) k_main(
    const float* __restrict__ x, const float* __restrict__ w3d,
    float* __restrict__ out) {
    extern __shared__ char sm[];
    int h = blockIdx.x, b = blockIdx.y;
    int tid = threadIdx.x;
    int lane = tid & 31, wid = tid >> 5;

    // ---- cp.async stage of conv halo chunk k into buffer k&1 ----
    auto stage = [&](int k) {
        int c0 = k * 64;
        float* buf = (float*)(sm + SMO_XS) + (k & 1) * XS_CHUNK;
        unsigned dstb = s2u(buf);
        const float4* x4 = (const float4*)x;
        for (int i = tid; i < 3168; i += 512) {
            int w4 = i & 15, rem = i >> 4;
            int dh = rem % 3, cc = rem / 3;
            int cg = c0 - 1 + cc, hg = h - 1 + dh;
            bool ok = ((unsigned)cg < 512u) && ((unsigned)hg < 64u);
            const float4* src = ok ? (x4 + (((size_t)(b * 512 + cg) * 64 + hg) * 16 + w4)) : x4;
            int sz = ok ? 16 : 0;
            asm volatile("cp.async.cg.shared.global [%0], [%1], 16, %2;\n"
                         :: "r"(dstb + (unsigned)i * 16), "l"((const void*)src), "r"(sz));
        }
        asm volatile("cp.async.commit_group;\n" ::);
    };

    // Prefetch conv chunks 0,1 early (overlap with A/S staging + MMA)
    stage(0);
    stage(1);

    // ---- Phase 0: stage A (bf16) + build S (bf16) ----
    {
        const uint4* src = (const uint4*)(g_cAb + (size_t)b * Cn * A_LD);
        uint4* dst = (uint4*)(sm + SMO_A);
#pragma unroll
        for (int i = tid; i < 4608; i += 512) dst[i] = src[i];
        const float* ho = g_hout + b * Rn * Hn;
        const float* wo = g_wout + b * Rn * Wn;
        __nv_bfloat16* S = (__nv_bfloat16*)(sm + SMO_S);
        for (int i = tid; i < 4096; i += 512) {
            int r = i >> 6, w = i & 63;
            S[r * A_LD + w] = __float2bfloat16(ho[r * 64 + h] * wo[r * 64 + w]);
        }
    }
    __syncthreads();

    // ---- Phase 1: MMA. Warp owns c rows [wid*32, wid*32+32), all 64 w ----
    float acc[2][8][4];
#pragma unroll
    for (int i = 0; i < 2; i++)
#pragma unroll
        for (int j = 0; j < 8; j++)
#pragma unroll
            for (int r = 0; r < 4; r++) acc[i][j][r] = 0.f;

    {
        unsigned aBase = s2u(sm + SMO_A);
        unsigned sBase = s2u(sm + SMO_S);
        int aRow = lane & 15;
        unsigned aColOff = (unsigned)(lane >> 4) * 16u;  // bytes (k half)
        int li = lane & 7;
        int bRowOff = li + ((lane & 8) ? 8 : 0);
        int bColOff = (lane & 16) ? 8 : 0;
#pragma unroll
        for (int ks = 0; ks < 4; ks++) {
            int k0 = ks * 16;
            unsigned a_frag[2][4];
#pragma unroll
            for (int i = 0; i < 2; i++) {
                unsigned ad = aBase + (unsigned)((wid * 32 + i * 16 + aRow) * A_LD + k0) * 2u + aColOff;
                asm volatile("ldmatrix.sync.aligned.m8n8.x4.shared.b16 {%0,%1,%2,%3}, [%4];\n"
                             : "=r"(a_frag[i][0]), "=r"(a_frag[i][1]),
                               "=r"(a_frag[i][2]), "=r"(a_frag[i][3])
                             : "r"(ad));
            }
#pragma unroll
            for (int nb = 0; nb < 4; nb++) {
                unsigned bd = sBase + (unsigned)((k0 + bRowOff) * A_LD + nb * 16 + bColOff) * 2u;
                unsigned bq0, bq1, bq2, bq3;
                asm volatile("ldmatrix.sync.aligned.m8n8.x4.trans.shared.b16 {%0,%1,%2,%3}, [%4];\n"
                             : "=r"(bq0), "=r"(bq1), "=r"(bq2), "=r"(bq3) : "r"(bd));
#pragma unroll
                for (int i = 0; i < 2; i++) {
                    asm volatile(
                        "mma.sync.aligned.m16n8k16.row.col.f32.bf16.bf16.f32 "
                        "{%0,%1,%2,%3},{%4,%5,%6,%7},{%8,%9},{%0,%1,%2,%3};\n"
                        : "+f"(acc[i][2 * nb][0]), "+f"(acc[i][2 * nb][1]),
                          "+f"(acc[i][2 * nb][2]), "+f"(acc[i][2 * nb][3])
                        : "r"(a_frag[i][0]), "r"(a_frag[i][1]),
                          "r"(a_frag[i][2]), "r"(a_frag[i][3]),
                          "r"(bq0), "r"(bq1));
                    asm volatile(
                        "mma.sync.aligned.m16n8k16.row.col.f32.bf16.bf16.f32 "
                        "{%0,%1,%2,%3},{%4,%5,%6,%7},{%8,%9},{%0,%1,%2,%3};\n"
                        : "+f"(acc[i][2 * nb + 1][0]), "+f"(acc[i][2 * nb + 1][1]),
                          "+f"(acc[i][2 * nb + 1][2]), "+f"(acc[i][2 * nb + 1][3])
                        : "r"(a_frag[i][0]), "r"(a_frag[i][1]),
                          "r"(a_frag[i][2]), "r"(a_frag[i][3]),
                          "r"(bq2), "r"(bq3));
                }
            }
        }
    }
    __syncthreads();  // A region dead after this

    // ---- Phase 2: softmax over c (registers + smem partials), g -> bf16 smem
    float* wred = (float*)(sm + SMO_WRED);
    float* mcol = (float*)(sm + SMO_MCOL);
    float* icol = (float*)(sm + SMO_ICOL);
    int l4 = lane & 3;

#pragma unroll
    for (int j = 0; j < 8; j++)
#pragma unroll
        for (int par = 0; par < 2; par++) {
            float m = fmaxf(fmaxf(acc[0][j][par], acc[0][j][2 + par]),
                            fmaxf(acc[1][j][par], acc[1][j][2 + par]));
            m = fmaxf(m, __shfl_xor_sync(0xffffffffu, m, 4));
            m = fmaxf(m, __shfl_xor_sync(0xffffffffu, m, 8));
            m = fmaxf(m, __shfl_xor_sync(0xffffffffu, m, 16));
            if (lane < 4) wred[wid * 64 + j * 8 + l4 * 2 + par] = m;
        }
    __syncthreads();
    if (tid < 64) {
        float m = wred[tid];
#pragma unroll
        for (int k = 1; k < 16; k++) m = fmaxf(m, wred[k * 64 + tid]);
        mcol[tid] = m;
    }
    __syncthreads();
#pragma unroll
    for (int j = 0; j < 8; j++)
#pragma unroll
        for (int par = 0; par < 2; par++) {
            int w = j * 8 + l4 * 2 + par;
            float mv = mcol[w];
            float s = __expf(acc[0][j][par] - mv) + __expf(acc[0][j][2 + par] - mv)
                    + __expf(acc[1][j][par] - mv) + __expf(acc[1][j][2 + par] - mv);
            s += __shfl_xor_sync(0xffffffffu, s, 4);
            s += __shfl_xor_sync(0xffffffffu, s, 8);
            s += __shfl_xor_sync(0xffffffffu, s, 16);
            if (lane < 4) wred[wid * 64 + w] = s;
        }
    __syncthreads();
    if (tid < 64) {
        float s = wred[tid];
#pragma unroll
        for (int k = 1; k < 16; k++) s += wred[k * 64 + tid];
        icol[tid] = 1.f / s;
    }
    __syncthreads();
    {
        __nv_bfloat162* gsm = (__nv_bfloat162*)(sm + SMO_G);
#pragma unroll
        for (int i = 0; i < 2; i++)
#pragma unroll
            for (int half = 0; half < 2; half++) {
                int c = wid * 32 + i * 16 + (lane >> 2) + half * 8;
#pragma unroll
                for (int j = 0; j < 8; j++) {
                    int w0 = j * 8 + l4 * 2;
                    float g0 = __expf(acc[i][j][2 * half + 0] - mcol[w0]) * icol[w0];
                    float g1 = __expf(acc[i][j][2 * half + 1] - mcol[w0 + 1]) * icol[w0 + 1];
                    gsm[(c * 64 + w0) >> 1] = __floats2bfloat162_rn(g0, g1);
                }
            }
    }
    __syncthreads();

    // ---- Phase 3: conv3d + g*res + x, pipelined over 8 c-chunks ----
    float w3[27];
#pragma unroll
    for (int t = 0; t < 27; t++) w3[t] = __ldg(w3d + t);
    int cl = tid >> 3, wg = tid & 7;
    const __nv_bfloat16* gsmb = (const __nv_bfloat16*)(sm + SMO_G);

    for (int k = 0; k < 8; k++) {
        if (k == 7) asm volatile("cp.async.wait_group 0;\n" ::);
        else        asm volatile("cp.async.wait_group 1;\n" ::);
        __syncthreads();
        const float* xs = (const float*)(sm + SMO_XS) + (k & 1) * XS_CHUNK;

        float res[8];
#pragma unroll
        for (int j = 0; j < 8; j++) res[j] = 0.f;
        float4 xi0 = make_float4(0.f, 0.f, 0.f, 0.f), xi1 = xi0;
#pragma unroll
        for (int dc = 0; dc < 3; dc++)
#pragma unroll
            for (int dh = 0; dh < 3; dh++) {
                const float* row = xs + (cl + dc) * 192 + dh * 64 + wg * 8;
                float4 m0 = *(const float4*)row;
                float4 m1 = *(const float4*)(row + 4);
                float left  = (wg == 0) ? 0.f : row[-1];
                float right = (wg == 7) ? 0.f : row[8];
                if (dc == 1 && dh == 1) { xi0 = m0; xi1 = m1; }
                float v[10] = {left, m0.x, m0.y, m0.z, m0.w,
                               m1.x, m1.y, m1.z, m1.w, right};
                int t = (dc * 3 + dh) * 3;
                float k0 = w3[t], k1 = w3[t + 1], k2 = w3[t + 2];
#pragma unroll
                for (int j = 0; j < 8; j++)
                    res[j] += k0 * v[j] + k1 * v[j + 1] + k2 * v[j + 2];
            }

        int c = k * 64 + cl;
        uint4 gv = *(const uint4*)(gsmb + c * 64 + wg * 8);
        const __nv_bfloat162* gp = (const __nv_bfloat162*)&gv;
        float xin[8] = {xi0.x, xi0.y, xi0.z, xi0.w, xi1.x, xi1.y, xi1.z, xi1.w};
        float o[8];
#pragma unroll
        for (int j2 = 0; j2 < 4; j2++) {
            float2 gf = __bfloat1622float2(gp[j2]);
            o[2 * j2]     = res[2 * j2]     * gf.x + xin[2 * j2];
            o[2 * j2 + 1] = res[2 * j2 + 1] * gf.y + xin[2 * j2 + 1];
        }

        float* op = out + (((size_t)(b * 512 + c) * 64 + h) * 64 + wg * 8);
        *(float4*)(op)     = make_float4(o[0], o[1], o[2], o[3]);
        *(float4*)(op + 4) = make_float4(o[4], o[5], o[6], o[7]);
        __syncthreads();
        if (k + 2 < 8) stage(k + 2);
    }
}

// ---------------------------------------------------------------------------
extern "C" void kernel_launch(void* const* d_in, const int* in_sizes, int n_in,
                              void* d_out, int out_size) {
    const float* x   = (const float*)d_in[0];
    const float* w_c = (const float*)d_in[1];
    const float* a_c = (const float*)d_in[2];
    const float* w_w = (const float*)d_in[3];
    const float* a_w = (const float*)d_in[4];
    const float* w_h = (const float*)d_in[5];
    const float* a_h = (const float*)d_in[6];
    const float* w3d = (const float*)d_in[7];
    float* out = (float*)d_out;

    cudaFuncSetAttribute(k_main, cudaFuncAttributeMaxDynamicSharedMemorySize, SM_BYTES);

    k_reduce<<<Bn * Cn, 256>>>(x);
    k_branches<<<Bn, 256>>>(w_c, a_c, w_w, a_w, w_h, a_h);
    dim3 grid(Hn, Bn);
    k_main<<<grid, 512, SM_BYTES>>>(x, w3d, out);
}

// round 5
// speedup vs baseline: 1.8539x; 1.2634x over previous
#include <cuda_runtime.h>
#include <cuda_bf16.h>
#include <cstdint>

#define Bn 16
#define Cn 512
#define Hn 64
#define Wn 64
#define Rn 64
#define A_LD 72   // padded bf16 row stride (144B: 16B-aligned, ldmatrix conflict-free)

// Scratch (device globals; no allocation allowed)
__device__ float g_sumC[Bn*Cn];
__device__ float g_partW[Bn*Cn*Wn];
__device__ float g_partH[Bn*Cn*Hn];
__device__ __align__(16) __nv_bfloat16 g_cAb[Bn*Cn*A_LD];  // A[b][c][r] bf16 padded
__device__ float g_wout[Bn*Rn*Wn];  // [b][r][w]
__device__ float g_hout[Bn*Rn*Hn];  // [b][r][h]
__device__ __align__(16) __nv_bfloat16 g_g[(size_t)Bn*Cn*Hn*Wn];  // softmax weights

__device__ __forceinline__ unsigned s2u(const void* p) {
    return (unsigned)__cvta_generic_to_shared(p);
}

// ---------------------------------------------------------------------------
// K1: per-(b,c) plane reductions: total sum, per-w column sums, per-h row sums
// ---------------------------------------------------------------------------
__global__ __launch_bounds__(256) void k_reduce(const float* __restrict__ x) {
    int plane = blockIdx.x;  // b*Cn + c
    const float4* x4 = (const float4*)(x + (size_t)plane * 4096);
    int tid = threadIdx.x;

    __shared__ float4 s4[256];
    __shared__ float  sh[256][4];

    float4 wacc = make_float4(0.f, 0.f, 0.f, 0.f);
    float hacc[4];
#pragma unroll
    for (int k = 0; k < 4; k++) {
        float4 f = x4[tid + 256 * k];
        wacc.x += f.x; wacc.y += f.y; wacc.z += f.z; wacc.w += f.w;
        hacc[k] = f.x + f.y + f.z + f.w;
    }
    s4[tid] = wacc;
    sh[tid][0] = hacc[0]; sh[tid][1] = hacc[1];
    sh[tid][2] = hacc[2]; sh[tid][3] = hacc[3];
    __syncthreads();

    if (tid < 16) {
        float4 t = s4[tid];
#pragma unroll
        for (int j = 1; j < 16; j++) {
            float4 u = s4[tid + 16 * j];
            t.x += u.x; t.y += u.y; t.z += u.z; t.w += u.w;
        }
        ((float4*)g_partW)[plane * 16 + tid] = t;
        s4[tid] = t;
    }
    if (tid >= 64 && tid < 128) {
        int h = tid - 64;
        int base = (h & 15) * 16;
        int k = h >> 4;
        float s = 0.f;
#pragma unroll
        for (int j = 0; j < 16; j++) s += sh[base + j][k];
        g_partH[plane * 64 + h] = s;
    }
    __syncthreads();
    if (tid == 0) {
        float tot = 0.f;
#pragma unroll
        for (int j = 0; j < 16; j++) {
            float4 u = s4[j];
            tot += u.x + u.y + u.z + u.w;
        }
        g_sumC[plane] = tot;
    }
}

// ---------------------------------------------------------------------------
// K2: finish gap means, 3-tap convs + PReLU for the three branches
// ---------------------------------------------------------------------------
__global__ __launch_bounds__(256) void k_branches(
    const float* __restrict__ w_c, const float* __restrict__ a_c,
    const float* __restrict__ w_w, const float* __restrict__ a_w,
    const float* __restrict__ w_h, const float* __restrict__ a_h) {
    int b = blockIdx.x, tid = threadIdx.x;
    __shared__ float gc[Cn + 2];
    __shared__ float gw[Wn + 2];
    __shared__ float gh[Hn + 2];
    __shared__ float red[4][64];

    for (int i = tid; i < Cn; i += 256)
        gc[i + 1] = g_sumC[b * Cn + i] * (1.f / 4096.f);
    if (tid == 0) {
        gc[0] = 0.f; gc[Cn + 1] = 0.f;
        gw[0] = 0.f; gw[Wn + 1] = 0.f;
        gh[0] = 0.f; gh[Hn + 1] = 0.f;
    }
    {
        int q = tid >> 6, w = tid & 63;
        float s = 0.f;
        const float* p = g_partW + ((size_t)(b * Cn + q * 128)) * 64 + w;
#pragma unroll 4
        for (int c = 0; c < 128; c++) s += p[c * 64];
        red[q][w] = s;
    }
    __syncthreads();
    if (tid < 64)
        gw[tid + 1] = (red[0][tid] + red[1][tid] + red[2][tid] + red[3][tid]) * (1.f / 32768.f);
    __syncthreads();
    {
        int q = tid >> 6, hh = tid & 63;
        float s = 0.f;
        const float* p = g_partH + ((size_t)(b * Cn + q * 128)) * 64 + hh;
#pragma unroll 4
        for (int c = 0; c < 128; c++) s += p[c * 64];
        red[q][hh] = s;
    }
    __syncthreads();
    if (tid < 64)
        gh[tid + 1] = (red[0][tid] + red[1][tid] + red[2][tid] + red[3][tid]) * (1.f / 32768.f);
    __syncthreads();

    float acv = a_c[0], awv = a_w[0], ahv = a_h[0];
    // channel branch -> bf16 A matrix [c][r] (row stride A_LD)
    for (int i = tid; i < Rn * Cn; i += 256) {
        int r = i >> 9, c = i & 511;
        float v = w_c[r * 3] * gc[c] + w_c[r * 3 + 1] * gc[c + 1] + w_c[r * 3 + 2] * gc[c + 2];
        v = (v >= 0.f) ? v : acv * v;
        g_cAb[((size_t)(b * Cn + c)) * A_LD + r] = __float2bfloat16(v);
    }
    for (int i = tid; i < Rn * Wn; i += 256) {
        int r = i >> 6, w = i & 63;
        float v = w_w[r * 3] * gw[w] + w_w[r * 3 + 1] * gw[w + 1] + w_w[r * 3 + 2] * gw[w + 2];
        g_wout[b * Rn * Wn + i] = (v >= 0.f) ? v : awv * v;
        float v2 = w_h[r * 3] * gh[w] + w_h[r * 3 + 1] * gh[w + 1] + w_h[r * 3 + 2] * gh[w + 2];
        g_hout[b * Rn * Hn + i] = (v2 >= 0.f) ? v2 : ahv * v2;
    }
}

// ---------------------------------------------------------------------------
// K3a: per-(b,h) block: tensor-core GEMM cp = A^T(bf16) @ S(bf16), softmax
// over c in registers, write g (bf16) to gmem coalesced.
// ---------------------------------------------------------------------------
#define SMO_A    0        // bf16 [512][A_LD]     = 73728 B (dead after MMA)
#define SMO_S    73728    // bf16 [64][A_LD]      = 9216 B
#define SMO_WRED 82944    // f32 [16][64]         = 4096 B
#define SMO_MCOL 87040    // f32 [64]
#define SMO_ICOL 87296    // f32 [64]
#define SMO_G    0        // bf16 [512][64]       = 65536 B (overlaps A)
#define SMG_BYTES 87552

__global__ void __launch_bounds__(512) k_gemm(int dummy) {
    extern __shared__ char sm[];
    int h = blockIdx.x, b = blockIdx.y;
    int tid = threadIdx.x;
    int lane = tid & 31, wid = tid >> 5;

    // ---- Phase 0: stage A (bf16) + build S (bf16) ----
    {
        const uint4* src = (const uint4*)(g_cAb + (size_t)b * Cn * A_LD);
        uint4* dst = (uint4*)(sm + SMO_A);
#pragma unroll
        for (int i = tid; i < 4608; i += 512) dst[i] = src[i];
        const float* ho = g_hout + b * Rn * Hn;
        const float* wo = g_wout + b * Rn * Wn;
        __nv_bfloat16* S = (__nv_bfloat16*)(sm + SMO_S);
        for (int i = tid; i < 4096; i += 512) {
            int r = i >> 6, w = i & 63;
            S[r * A_LD + w] = __float2bfloat16(ho[r * 64 + h] * wo[r * 64 + w]);
        }
    }
    __syncthreads();

    // ---- Phase 1: MMA. Warp owns c rows [wid*32, wid*32+32), all 64 w ----
    float acc[2][8][4];
#pragma unroll
    for (int i = 0; i < 2; i++)
#pragma unroll
        for (int j = 0; j < 8; j++)
#pragma unroll
            for (int r = 0; r < 4; r++) acc[i][j][r] = 0.f;

    {
        unsigned aBase = s2u(sm + SMO_A);
        unsigned sBase = s2u(sm + SMO_S);
        int aRow = lane & 15;
        unsigned aColOff = (unsigned)(lane >> 4) * 16u;  // bytes (k half)
        int li = lane & 7;
        int bRowOff = li + ((lane & 8) ? 8 : 0);
        int bColOff = (lane & 16) ? 8 : 0;
#pragma unroll
        for (int ks = 0; ks < 4; ks++) {
            int k0 = ks * 16;
            unsigned a_frag[2][4];
#pragma unroll
            for (int i = 0; i < 2; i++) {
                unsigned ad = aBase + (unsigned)((wid * 32 + i * 16 + aRow) * A_LD + k0) * 2u + aColOff;
                asm volatile("ldmatrix.sync.aligned.m8n8.x4.shared.b16 {%0,%1,%2,%3}, [%4];\n"
                             : "=r"(a_frag[i][0]), "=r"(a_frag[i][1]),
                               "=r"(a_frag[i][2]), "=r"(a_frag[i][3])
                             : "r"(ad));
            }
#pragma unroll
            for (int nb = 0; nb < 4; nb++) {
                unsigned bd = sBase + (unsigned)((k0 + bRowOff) * A_LD + nb * 16 + bColOff) * 2u;
                unsigned bq0, bq1, bq2, bq3;
                asm volatile("ldmatrix.sync.aligned.m8n8.x4.trans.shared.b16 {%0,%1,%2,%3}, [%4];\n"
                             : "=r"(bq0), "=r"(bq1), "=r"(bq2), "=r"(bq3) : "r"(bd));
#pragma unroll
                for (int i = 0; i < 2; i++) {
                    asm volatile(
                        "mma.sync.aligned.m16n8k16.row.col.f32.bf16.bf16.f32 "
                        "{%0,%1,%2,%3},{%4,%5,%6,%7},{%8,%9},{%0,%1,%2,%3};\n"
                        : "+f"(acc[i][2 * nb][0]), "+f"(acc[i][2 * nb][1]),
                          "+f"(acc[i][2 * nb][2]), "+f"(acc[i][2 * nb][3])
                        : "r"(a_frag[i][0]), "r"(a_frag[i][1]),
                          "r"(a_frag[i][2]), "r"(a_frag[i][3]),
                          "r"(bq0), "r"(bq1));
                    asm volatile(
                        "mma.sync.aligned.m16n8k16.row.col.f32.bf16.bf16.f32 "
                        "{%0,%1,%2,%3},{%4,%5,%6,%7},{%8,%9},{%0,%1,%2,%3};\n"
                        : "+f"(acc[i][2 * nb + 1][0]), "+f"(acc[i][2 * nb + 1][1]),
                          "+f"(acc[i][2 * nb + 1][2]), "+f"(acc[i][2 * nb + 1][3])
                        : "r"(a_frag[i][0]), "r"(a_frag[i][1]),
                          "r"(a_frag[i][2]), "r"(a_frag[i][3]),
                          "r"(bq2), "r"(bq3));
                }
            }
        }
    }
    __syncthreads();  // A region dead after this

    // ---- Phase 2: softmax over c (registers + smem partials), g -> bf16 smem
    float* wred = (float*)(sm + SMO_WRED);
    float* mcol = (float*)(sm + SMO_MCOL);
    float* icol = (float*)(sm + SMO_ICOL);
    int l4 = lane & 3;

#pragma unroll
    for (int j = 0; j < 8; j++)
#pragma unroll
        for (int par = 0; par < 2; par++) {
            float m = fmaxf(fmaxf(acc[0][j][par], acc[0][j][2 + par]),
                            fmaxf(acc[1][j][par], acc[1][j][2 + par]));
            m = fmaxf(m, __shfl_xor_sync(0xffffffffu, m, 4));
            m = fmaxf(m, __shfl_xor_sync(0xffffffffu, m, 8));
            m = fmaxf(m, __shfl_xor_sync(0xffffffffu, m, 16));
            if (lane < 4) wred[wid * 64 + j * 8 + l4 * 2 + par] = m;
        }
    __syncthreads();
    if (tid < 64) {
        float m = wred[tid];
#pragma unroll
        for (int k = 1; k < 16; k++) m = fmaxf(m, wred[k * 64 + tid]);
        mcol[tid] = m;
    }
    __syncthreads();
#pragma unroll
    for (int j = 0; j < 8; j++)
#pragma unroll
        for (int par = 0; par < 2; par++) {
            int w = j * 8 + l4 * 2 + par;
            float mv = mcol[w];
            float s = __expf(acc[0][j][par] - mv) + __expf(acc[0][j][2 + par] - mv)
                    + __expf(acc[1][j][par] - mv) + __expf(acc[1][j][2 + par] - mv);
            s += __shfl_xor_sync(0xffffffffu, s, 4);
            s += __shfl_xor_sync(0xffffffffu, s, 8);
            s += __shfl_xor_sync(0xffffffffu, s, 16);
            if (lane < 4) wred[wid * 64 + w] = s;
        }
    __syncthreads();
    if (tid < 64) {
        float s = wred[tid];
#pragma unroll
        for (int k = 1; k < 16; k++) s += wred[k * 64 + tid];
        icol[tid] = 1.f / s;
    }
    __syncthreads();
    {
        __nv_bfloat162* gsm = (__nv_bfloat162*)(sm + SMO_G);
#pragma unroll
        for (int i = 0; i < 2; i++)
#pragma unroll
            for (int half = 0; half < 2; half++) {
                int c = wid * 32 + i * 16 + (lane >> 2) + half * 8;
#pragma unroll
                for (int j = 0; j < 8; j++) {
                    int w0 = j * 8 + l4 * 2;
                    float g0 = __expf(acc[i][j][2 * half + 0] - mcol[w0]) * icol[w0];
                    float g1 = __expf(acc[i][j][2 * half + 1] - mcol[w0 + 1]) * icol[w0 + 1];
                    gsm[(c * 64 + w0) >> 1] = __floats2bfloat162_rn(g0, g1);
                }
            }
    }
    __syncthreads();

    // ---- Phase 3: write g to gmem, coalesced (8 uint4 per c-row) ----
    {
        const uint4* gs4 = (const uint4*)(sm + SMO_G);
        uint4* gg = (uint4*)g_g;
        for (int i = tid; i < 4096; i += 512) {
            int c = i >> 3, col = i & 7;
            gg[(((size_t)(b * 512 + c)) * 64 + h) * 8 + col] = gs4[i];
        }
    }
}

// ---------------------------------------------------------------------------
// K3b: stencil conv3d + g*res + x. Block = (b, 32-c-tile, 8-h-tile), 256 thr,
// 2 CTAs/SM. One-shot tile load, fully-unrolled input-stationary compute.
// ---------------------------------------------------------------------------
#define SMC_BYTES (34 * 10 * 64 * 4)  // 87040

__global__ void __launch_bounds__(256, 2) k_conv(
    const float* __restrict__ x, const float* __restrict__ w3d,
    float* __restrict__ out) {
    extern __shared__ float xt[];  // [34 c][10 h][64 w]
    int h0 = blockIdx.x * 8;
    int c0 = blockIdx.y * 32;
    int b  = blockIdx.z;
    int tid = threadIdx.x;

    // ---- load halo tile via cp.async with zero-fill ----
    {
        unsigned dstb = s2u(xt);
        const float4* x4 = (const float4*)x;
        for (int i = tid; i < 5440; i += 256) {
            int w4 = i & 15, rest = i >> 4;
            int hi = rest % 10, ci = rest / 10;
            int cg = c0 - 1 + ci, hg = h0 - 1 + hi;
            bool ok = ((unsigned)cg < 512u) && ((unsigned)hg < 64u);
            const float4* src = ok ? (x4 + (((size_t)(b * 512 + cg) * 64 + hg) * 16 + w4)) : x4;
            int sz = ok ? 16 : 0;
            asm volatile("cp.async.cg.shared.global [%0], [%1], 16, %2;\n"
                         :: "r"(dstb + (unsigned)i * 16), "l"((const void*)src), "r"(sz));
        }
        asm volatile("cp.async.commit_group;\n" ::);
        asm volatile("cp.async.wait_group 0;\n" ::);
    }
    __syncthreads();

    int wg = tid & 7, hq = (tid >> 3) & 7, cq = tid >> 6;
    float w3[27];
#pragma unroll
    for (int t = 0; t < 27; t++) w3[t] = __ldg(w3d + t);

    float res[8][8];
#pragma unroll
    for (int i = 0; i < 8; i++)
#pragma unroll
        for (int j = 0; j < 8; j++) res[i][j] = 0.f;

    // input-stationary: each input row (ii, dhi) loaded once, feeds <=3 c-outs
#pragma unroll
    for (int ii = 0; ii < 10; ii++) {
#pragma unroll
        for (int dhi = 0; dhi < 3; dhi++) {
            const float* row = xt + ((cq * 8 + ii) * 10 + (hq + dhi)) * 64 + wg * 8;
            float4 m0 = *(const float4*)row;
            float4 m1 = *(const float4*)(row + 4);
            float left  = (wg == 0) ? 0.f : row[-1];
            float right = (wg == 7) ? 0.f : row[8];
            float v[10] = {left, m0.x, m0.y, m0.z, m0.w,
                           m1.x, m1.y, m1.z, m1.w, right};
#pragma unroll
            for (int dc = 0; dc < 3; dc++) {
                int cc = ii - dc;
                if (cc < 0 || cc > 7) continue;
                int t = (dc * 3 + dhi) * 3;
                float k0 = w3[t], k1 = w3[t + 1], k2 = w3[t + 2];
#pragma unroll
                for (int j = 0; j < 8; j++)
                    res[cc][j] += k0 * v[j] + k1 * v[j + 1] + k2 * v[j + 2];
            }
        }
    }

    // ---- epilogue: o = res * g + x ----
    int h = h0 + hq;
#pragma unroll
    for (int cc = 0; cc < 8; cc++) {
        int c = c0 + cq * 8 + cc;
        const float* ctr = xt + ((cq * 8 + cc + 1) * 10 + (hq + 1)) * 64 + wg * 8;
        float4 xi0 = *(const float4*)ctr;
        float4 xi1 = *(const float4*)(ctr + 4);
        uint4 gv = *(const uint4*)(g_g + (((size_t)(b * 512 + c)) * 64 + h) * 64 + wg * 8);
        const __nv_bfloat162* gp = (const __nv_bfloat162*)&gv;
        float xin[8] = {xi0.x, xi0.y, xi0.z, xi0.w, xi1.x, xi1.y, xi1.z, xi1.w};
        float o[8];
#pragma unroll
        for (int j2 = 0; j2 < 4; j2++) {
            float2 gf = __bfloat1622float2(gp[j2]);
            o[2 * j2]     = res[cc][2 * j2]     * gf.x + xin[2 * j2];
            o[2 * j2 + 1] = res[cc][2 * j2 + 1] * gf.y + xin[2 * j2 + 1];
        }
        float* op = out + (((size_t)(b * 512 + c) * 64 + h) * 64 + wg * 8);
        *(float4*)(op)     = make_float4(o[0], o[1], o[2], o[3]);
        *(float4*)(op + 4) = make_float4(o[4], o[5], o[6], o[7]);
    }
}

// ---------------------------------------------------------------------------
extern "C" void kernel_launch(void* const* d_in, const int* in_sizes, int n_in,
                              void* d_out, int out_size) {
    const float* x   = (const float*)d_in[0];
    const float* w_c = (const float*)d_in[1];
    const float* a_c = (const float*)d_in[2];
    const float* w_w = (const float*)d_in[3];
    const float* a_w = (const float*)d_in[4];
    const float* w_h = (const float*)d_in[5];
    const float* a_h = (const float*)d_in[6];
    const float* w3d = (const float*)d_in[7];
    float* out = (float*)d_out;

    cudaFuncSetAttribute(k_gemm, cudaFuncAttributeMaxDynamicSharedMemorySize, SMG_BYTES);
    cudaFuncSetAttribute(k_conv, cudaFuncAttributeMaxDynamicSharedMemorySize, SMC_BYTES);

    k_reduce<<<Bn * Cn, 256>>>(x);
    k_branches<<<Bn, 256>>>(w_c, a_c, w_w, a_w, w_h, a_h);
    dim3 gridG(Hn, Bn);
    k_gemm<<<gridG, 512, SMG_BYTES>>>(0);
    dim3 gridC(8, 16, Bn);
    k_conv<<<gridC, 256, SMC_BYTES>>>(x, w3d, out);
}